// round 1
// baseline (speedup 1.0000x reference)
#include <cuda_runtime.h>

// Problem constants (from reference setup_inputs)
#define K_DIM   2048
#define N_EXP   64
#define TM      64      // rows per CTA
#define TK      32      // K tile
#define THREADS 128
#define LDA     68      // padded smem row stride (floats), 16B-aligned (272B)
#define TOPK_TEMP 2.0f

__global__ __launch_bounds__(THREADS)
void dhr_gemm_route_kernel(const float* __restrict__ x,
                           const float* __restrict__ w,
                           const float* __restrict__ bias,
                           const int*   __restrict__ mat,
                           float* __restrict__ out)
{
    // One buffer, reused: GEMM stage = As[TK][LDA] + Bs[TK][LDA]
    // Epilogue stage = logits L[64][LDA]  (64*68 == 2*TK*LDA exactly)
    __shared__ __align__(16) float sm[2 * TK * LDA];
    float* As = sm;                 // [TK][LDA]  : As[k][row]
    float* Bs = sm + TK * LDA;      // [TK][LDA]  : Bs[k][expert]

    const int t  = threadIdx.x;
    const int tx = t & 15;          // expert group: experts tx*4 .. tx*4+3
    const int ty = t >> 4;          // row group:    rows    ty*8 .. ty*8+7
    const int row0 = blockIdx.x * TM;

    float acc[8][4];
    #pragma unroll
    for (int i = 0; i < 8; i++)
        #pragma unroll
        for (int j = 0; j < 4; j++)
            acc[i][j] = 0.0f;

    const float* xg = x + (long)row0 * K_DIM;

    // Register-staged double buffering of global loads.
    float4 ra[4], rb[4];
    #pragma unroll
    for (int s = 0; s < 4; s++) {
        int idx = s * THREADS + t;          // 0..511 float4 slots
        int r = idx >> 3;                   // 64 rows, 8 float4 per row
        int c = (idx & 7) << 2;             // 0..28
        ra[s] = *(const float4*)(xg + (long)r * K_DIM + c);
        rb[s] = *(const float4*)(w  + (long)r * K_DIM + c);
    }

    const int NBLK = K_DIM / TK;            // 64
    for (int kb = 0; kb < NBLK; kb++) {
        // Stage current tile into SMEM (transposed: [k][row])
        #pragma unroll
        for (int s = 0; s < 4; s++) {
            int idx = s * THREADS + t;
            int r = idx >> 3;
            int c = (idx & 7) << 2;
            As[(c + 0) * LDA + r] = ra[s].x;
            As[(c + 1) * LDA + r] = ra[s].y;
            As[(c + 2) * LDA + r] = ra[s].z;
            As[(c + 3) * LDA + r] = ra[s].w;
            Bs[(c + 0) * LDA + r] = rb[s].x;
            Bs[(c + 1) * LDA + r] = rb[s].y;
            Bs[(c + 2) * LDA + r] = rb[s].z;
            Bs[(c + 3) * LDA + r] = rb[s].w;
        }
        __syncthreads();

        // Prefetch next tile into registers (hidden under compute)
        if (kb + 1 < NBLK) {
            int k0 = (kb + 1) * TK;
            #pragma unroll
            for (int s = 0; s < 4; s++) {
                int idx = s * THREADS + t;
                int r = idx >> 3;
                int c = (idx & 7) << 2;
                ra[s] = *(const float4*)(xg + (long)r * K_DIM + k0 + c);
                rb[s] = *(const float4*)(w  + (long)r * K_DIM + k0 + c);
            }
        }

        // 8x4 register-tile outer product
        #pragma unroll
        for (int k = 0; k < TK; k++) {
            float4 a0 = *(const float4*)&As[k * LDA + ty * 8];
            float4 a1 = *(const float4*)&As[k * LDA + ty * 8 + 4];
            float4 bb = *(const float4*)&Bs[k * LDA + tx * 4];
            float av[8] = {a0.x, a0.y, a0.z, a0.w, a1.x, a1.y, a1.z, a1.w};
            float bv[4] = {bb.x, bb.y, bb.z, bb.w};
            #pragma unroll
            for (int i = 0; i < 8; i++)
                #pragma unroll
                for (int j = 0; j < 4; j++)
                    acc[i][j] = fmaf(av[i], bv[j], acc[i][j]);
        }
        __syncthreads();
    }

    // ---------------- Epilogue: routing ----------------
    // Reuse sm as logits L[64][LDA]
    float* L = sm;   // safe: last loop iteration ended with __syncthreads()

    #pragma unroll
    for (int i = 0; i < 8; i++) {
        int r = ty * 8 + i;
        #pragma unroll
        for (int j = 0; j < 4; j++) {
            int e = tx * 4 + j;
            L[r * LDA + e] = acc[i][j] + __ldg(&bias[e]);
        }
    }
    __syncthreads();

    if (t < TM) {
        // runtime branch selection (matches jax.lax.cond on any(maturity==0))
        bool any_immature = false;
        #pragma unroll 8
        for (int e = 0; e < N_EXP; e++)
            any_immature |= (__ldg(&mat[e]) == 0);

        float* row = &L[t * LDA];
        if (!any_immature) {
            // top-2 with strict '>' scan == jax top_k lower-index tie-break
            float v1 = -__int_as_float(0x7f800000), v2 = v1;
            int i1 = 0, i2 = 0;
            #pragma unroll 8
            for (int e = 0; e < N_EXP; e++) {
                float v = row[e];
                if (v > v1)      { v2 = v1; i2 = i1; v1 = v; i1 = e; }
                else if (v > v2) { v2 = v;  i2 = e; }
            }
            float e2 = __expf(v2 - v1);
            float inv = 1.0f / (1.0f + e2);
            float p1 = inv;
            float p2 = e2 * inv;
            #pragma unroll 8
            for (int e = 0; e < N_EXP; e++) row[e] = 0.0f;
            row[i1] = p1;
            row[i2] = p2;
        } else {
            // temperature softmax over all experts
            float m = -__int_as_float(0x7f800000);
            #pragma unroll 8
            for (int e = 0; e < N_EXP; e++) m = fmaxf(m, row[e]);
            float s = 0.0f;
            float tmp[N_EXP];
            #pragma unroll 8
            for (int e = 0; e < N_EXP; e++) {
                float v = __expf((row[e] - m) * (1.0f / TOPK_TEMP));
                tmp[e] = v; s += v;
            }
            float invs = 1.0f / s;
            #pragma unroll 8
            for (int e = 0; e < N_EXP; e++) row[e] = tmp[e] * invs;
        }
    }
    __syncthreads();

    // Coalesced float4 store of the 64x64 tile
    #pragma unroll
    for (int s = 0; s < 8; s++) {
        int idx = s * THREADS + t;          // 0..1023 float4 slots
        int r = idx >> 4;                   // 16 float4 per row
        int c = (idx & 15) << 2;
        float4 v = *(const float4*)&L[r * LDA + c];
        *(float4*)(out + (long)(row0 + r) * N_EXP + c) = v;
    }
}

extern "C" void kernel_launch(void* const* d_in, const int* in_sizes, int n_in,
                              void* d_out, int out_size)
{
    const float* x    = (const float*)d_in[0];   // [16384, 2048]
    const float* w    = (const float*)d_in[1];   // [64, 2048]
    const float* b    = (const float*)d_in[2];   // [64]
    const int*   mat  = (const int*)  d_in[3];   // [64]
    float* out = (float*)d_out;                  // [16384, 64]

    int rows = in_sizes[0] / K_DIM;              // 16384
    int grid = rows / TM;                        // 256
    dhr_gemm_route_kernel<<<grid, THREADS>>>(x, w, b, mat, out);
}

// round 2
// speedup vs baseline: 2.3914x; 2.3914x over previous
#include <cuda_runtime.h>
#include <cstdint>

#define K_DIM   2048
#define N_EXP   64
#define TM      128     // rows per CTA
#define TK      64      // K per stage
#define NKT     32      // K_DIM / TK
#define THREADS 256
#define LDL     68      // logits row stride (floats)
#define TOPK_TEMP 2.0f

// pack two fp32 -> bf16x2, f0 in LOWER half (unambiguous via vector mov)
__device__ __forceinline__ uint32_t pack2(float f0, float f1) {
    uint32_t r;
    asm("{.reg .b16 l, h;\n\t"
        "cvt.rn.bf16.f32 l, %1;\n\t"
        "cvt.rn.bf16.f32 h, %2;\n\t"
        "mov.b32 %0, {l, h};}\n" : "=r"(r) : "f"(f0), "f"(f1));
    return r;
}

// split (f0,f1) into hi bf16x2 and lo (residual) bf16x2
__device__ __forceinline__ void split2(float f0, float f1, uint32_t &h, uint32_t &l) {
    h = pack2(f0, f1);
    float h0 = __uint_as_float(h << 16);          // bf16(f0) widened (exact)
    float h1 = __uint_as_float(h & 0xFFFF0000u);  // bf16(f1) widened (exact)
    l = pack2(f0 - h0, f1 - h1);                  // residuals exact in fp32
}

__device__ __forceinline__ void mma16816(float *d,
                                         uint32_t a0, uint32_t a1, uint32_t a2, uint32_t a3,
                                         uint32_t b0, uint32_t b1) {
    asm volatile("mma.sync.aligned.m16n8k16.row.col.f32.bf16.bf16.f32 "
                 "{%0,%1,%2,%3}, {%4,%5,%6,%7}, {%8,%9}, {%0,%1,%2,%3};"
                 : "+f"(d[0]), "+f"(d[1]), "+f"(d[2]), "+f"(d[3])
                 : "r"(a0), "r"(a1), "r"(a2), "r"(a3), "r"(b0), "r"(b1));
}

__global__ __launch_bounds__(THREADS, 1)
void dhr_mma_kernel(const float* __restrict__ x,
                    const float* __restrict__ w,
                    const float* __restrict__ bias,
                    const int*   __restrict__ mat,
                    float* __restrict__ out)
{
    // 34.8KB: during mainloop = two 16KB B-fragment stages; epilogue = logits[128][68]
    __shared__ __align__(16) float sm[TM * LDL];
    uint32_t* Bst = (uint32_t*)sm;   // stage word base: 0 / 4096

    const int t    = threadIdx.x;
    const int wid  = t >> 5;
    const int lane = t & 31;
    const int q    = lane & 3;       // threadID_in_group
    const int g    = lane >> 2;      // groupID (row within 8)
    const long rowBase = (long)blockIdx.x * TM;
    const int warpRow  = wid * 16;   // 8 warps x 16 rows = 128

    // A gmem pointers for this lane's fragment elements
    const float* pA0 = x + (rowBase + warpRow + g) * K_DIM + 2 * q;  // row g
    const float* pA1 = pA0 + 8 * K_DIM;                              // row g+8

    // B fill: thread t owns kpair bp (fixed) and n = bn0 + 8*i
    const int bp  = t & 31;                 // kpair within 64-K tile
    const int bks = bp >> 3;                // kstep 0..3
    const int brg = (bp >> 2) & 1;          // frag reg 0/1
    const int bq  = bp & 3;
    const int bn0 = t >> 5;                 // 0..7
    const int bln = (bn0 << 2) | bq;        // dest lane slot
    const float* pW = w + bn0 * K_DIM + 2 * bp;  // +8*i*K_DIM per iter, +K0

    float acc[8][4];
    #pragma unroll
    for (int i = 0; i < 8; i++)
        acc[i][0] = acc[i][1] = acc[i][2] = acc[i][3] = 0.f;

    // ---- prologue: fill B stage 0, prefetch A tile 0 ----
    #pragma unroll
    for (int i = 0; i < 8; i++) {
        float2 wv = *(const float2*)(pW + i * 8 * K_DIM);
        uint32_t h, l; split2(wv.x, wv.y, h, l);
        uint32_t* dst = Bst + (((bks * 8 + i) * 32 + bln) << 2);
        dst[brg] = h; dst[2 + brg] = l;
    }
    float2 ra[4][4];
    #pragma unroll
    for (int ks = 0; ks < 4; ks++) {
        ra[ks][0] = *(const float2*)(pA0 + ks * 16);
        ra[ks][1] = *(const float2*)(pA1 + ks * 16);
        ra[ks][2] = *(const float2*)(pA0 + ks * 16 + 8);
        ra[ks][3] = *(const float2*)(pA1 + ks * 16 + 8);
    }
    __syncthreads();

    // ---- mainloop ----
    float2 wreg[8];
    for (int kt = 0; kt < NKT; kt++) {
        const int sr  = (kt & 1) << 12;         // read stage (words)
        const int sw  = ((kt + 1) & 1) << 12;   // write stage
        const int k0n = (kt + 1) * TK;

        // prefetch w for next tile (latency hidden by mma below)
        if (kt + 1 < NKT) {
            #pragma unroll
            for (int i = 0; i < 8; i++)
                wreg[i] = *(const float2*)(pW + k0n + i * 8 * K_DIM);
        }

        // convert current A tile (registers -> bf16 hi/lo fragments)
        uint32_t ah[4][4], al[4][4];
        #pragma unroll
        for (int ks = 0; ks < 4; ks++)
            #pragma unroll
            for (int j = 0; j < 4; j++)
                split2(ra[ks][j].x, ra[ks][j].y, ah[ks][j], al[ks][j]);

        // prefetch A for next tile (ra free after convert)
        if (kt + 1 < NKT) {
            #pragma unroll
            for (int ks = 0; ks < 4; ks++) {
                ra[ks][0] = *(const float2*)(pA0 + k0n + ks * 16);
                ra[ks][1] = *(const float2*)(pA1 + k0n + ks * 16);
                ra[ks][2] = *(const float2*)(pA0 + k0n + ks * 16 + 8);
                ra[ks][3] = *(const float2*)(pA1 + k0n + ks * 16 + 8);
            }
        }

        // 4 ksteps x 8 n-tiles x 3 split terms
        #pragma unroll
        for (int ks = 0; ks < 4; ks++) {
            #pragma unroll
            for (int tt = 0; tt < 8; tt++) {
                uint4 bf = *(const uint4*)(Bst + sr + (((ks * 8 + tt) * 32 + lane) << 2));
                mma16816(acc[tt], ah[ks][0], ah[ks][1], ah[ks][2], ah[ks][3], bf.x, bf.y);  // hi*hi
                mma16816(acc[tt], ah[ks][0], ah[ks][1], ah[ks][2], ah[ks][3], bf.z, bf.w);  // hi*lo
                mma16816(acc[tt], al[ks][0], al[ks][1], al[ks][2], al[ks][3], bf.x, bf.y);  // lo*hi
            }
        }

        // convert + store w fragments for next tile
        if (kt + 1 < NKT) {
            #pragma unroll
            for (int i = 0; i < 8; i++) {
                uint32_t h, l; split2(wreg[i].x, wreg[i].y, h, l);
                uint32_t* dst = Bst + sw + (((bks * 8 + i) * 32 + bln) << 2);
                dst[brg] = h; dst[2 + brg] = l;
            }
        }
        __syncthreads();
    }

    // ---- epilogue: bias + logits to SMEM ----
    float* L = sm;
    #pragma unroll
    for (int tt = 0; tt < 8; tt++) {
        int c = tt * 8 + 2 * q;
        float b0 = __ldg(&bias[c]);
        float b1 = __ldg(&bias[c + 1]);
        int r0 = warpRow + g;
        L[r0 * LDL + c]           = acc[tt][0] + b0;
        L[r0 * LDL + c + 1]       = acc[tt][1] + b1;
        L[(r0 + 8) * LDL + c]     = acc[tt][2] + b0;
        L[(r0 + 8) * LDL + c + 1] = acc[tt][3] + b1;
    }
    __syncthreads();

    // ---- routing: one thread per row ----
    if (t < TM) {
        bool any_immature = false;
        #pragma unroll 8
        for (int e = 0; e < N_EXP; e++)
            any_immature |= (__ldg(&mat[e]) == 0);

        float* row = &L[t * LDL];
        if (!any_immature) {
            float v1 = -__int_as_float(0x7f800000), v2 = v1;
            int i1 = 0, i2 = 0;
            #pragma unroll 8
            for (int e = 0; e < N_EXP; e++) {
                float v = row[e];
                if (v > v1)      { v2 = v1; i2 = i1; v1 = v; i1 = e; }
                else if (v > v2) { v2 = v;  i2 = e; }
            }
            float e2  = __expf(v2 - v1);
            float inv = 1.0f / (1.0f + e2);
            #pragma unroll 8
            for (int e = 0; e < N_EXP; e++) row[e] = 0.0f;
            row[i1] = inv;
            row[i2] = e2 * inv;
        } else {
            float m = -__int_as_float(0x7f800000);
            #pragma unroll 8
            for (int e = 0; e < N_EXP; e++) m = fmaxf(m, row[e]);
            float s = 0.0f;
            float tmp[N_EXP];
            #pragma unroll 8
            for (int e = 0; e < N_EXP; e++) {
                float v = __expf((row[e] - m) * (1.0f / TOPK_TEMP));
                tmp[e] = v; s += v;
            }
            float invs = 1.0f / s;
            #pragma unroll 8
            for (int e = 0; e < N_EXP; e++) row[e] = tmp[e] * invs;
        }
    }
    __syncthreads();

    // ---- coalesced store of 128x64 tile ----
    #pragma unroll
    for (int s = 0; s < (TM * N_EXP / 4) / THREADS; s++) {   // 8
        int idx = s * THREADS + t;
        int r = idx >> 4;
        int c = (idx & 15) << 2;
        float4 v = *(const float4*)&L[r * LDL + c];
        *(float4*)(out + (rowBase + r) * N_EXP + c) = v;
    }
}

extern "C" void kernel_launch(void* const* d_in, const int* in_sizes, int n_in,
                              void* d_out, int out_size)
{
    const float* x   = (const float*)d_in[0];   // [16384, 2048]
    const float* w   = (const float*)d_in[1];   // [64, 2048]
    const float* b   = (const float*)d_in[2];   // [64]
    const int*   mat = (const int*)  d_in[3];   // [64]
    float* out = (float*)d_out;                 // [16384, 64]

    int rows = in_sizes[0] / K_DIM;             // 16384
    int grid = rows / TM;                       // 128
    dhr_mma_kernel<<<grid, THREADS>>>(x, w, b, mat, out);
}

// round 3
// speedup vs baseline: 2.7203x; 1.1375x over previous
#include <cuda_runtime.h>
#include <cstdint>

#define K_DIM   2048
#define N_EXP   64
#define TM      128     // rows per CTA
#define TK      64      // K per tile
#define NKT     32      // K_DIM / TK
#define THREADS 256
#define ASTRIDE 72      // A smem row stride (floats) -> conflict-free frag LDS.64
#define ASTAGE  (TM * ASTRIDE)   // 9216 floats per stage
#define NSTAGE  3
#define BWORDS  4096    // uint32 words per B stage (hi+lo fragments)
#define LDL     72      // logits row stride (floats)
#define TOPK_TEMP 2.0f
#define SMEM_BYTES (NSTAGE * ASTAGE * 4 + 2 * BWORDS * 4)   // 143360

// pack two fp32 -> bf16x2 (f0 in LOWER half) in one instruction
__device__ __forceinline__ uint32_t pack2(float f0, float f1) {
    uint32_t r;
    asm("cvt.rn.bf16x2.f32 %0, %1, %2;" : "=r"(r) : "f"(f1), "f"(f0));
    return r;
}

// split (f0,f1) into hi bf16x2 + exact residual lo bf16x2
__device__ __forceinline__ void split2(float f0, float f1, uint32_t &h, uint32_t &l) {
    h = pack2(f0, f1);
    float h0 = __uint_as_float(h << 16);          // bf16(f0) widened (exact)
    float h1 = __uint_as_float(h & 0xFFFF0000u);  // bf16(f1) widened (exact)
    l = pack2(f0 - h0, f1 - h1);                  // residuals exact in fp32
}

__device__ __forceinline__ void mma16816(float *d,
                                         uint32_t a0, uint32_t a1, uint32_t a2, uint32_t a3,
                                         uint32_t b0, uint32_t b1) {
    asm volatile("mma.sync.aligned.m16n8k16.row.col.f32.bf16.bf16.f32 "
                 "{%0,%1,%2,%3}, {%4,%5,%6,%7}, {%8,%9}, {%0,%1,%2,%3};"
                 : "+f"(d[0]), "+f"(d[1]), "+f"(d[2]), "+f"(d[3])
                 : "r"(a0), "r"(a1), "r"(a2), "r"(a3), "r"(b0), "r"(b1));
}

__device__ __forceinline__ void cp16(uint32_t dst, const void* src) {
    asm volatile("cp.async.cg.shared.global [%0], [%1], 16;" :: "r"(dst), "l"(src));
}

__global__ __launch_bounds__(THREADS, 1)
void dhr_mma_async_kernel(const float* __restrict__ x,
                          const float* __restrict__ w,
                          const float* __restrict__ bias,
                          const int*   __restrict__ mat,
                          float* __restrict__ out)
{
    extern __shared__ __align__(16) float smem[];
    uint32_t* Bst = (uint32_t*)(smem + NSTAGE * ASTAGE);   // 2 x BWORDS

    const int t    = threadIdx.x;
    const int wid  = t >> 5;
    const int lane = t & 31;
    const int q    = lane & 3;
    const int g    = lane >> 2;
    const long rowBase = (long)blockIdx.x * TM;
    const int  warpRow = wid * 16;

    // cp.async A-chunk assignment: idx = ss*256+t -> (row, 16B-chunk)
    const uint32_t aSmem = (uint32_t)__cvta_generic_to_shared(smem);

    // B fill params (fragment order in SMEM, same as validated R2 layout)
    const int bp  = t & 31;
    const int bks = bp >> 3;
    const int brg = (bp >> 2) & 1;
    const int bn0 = t >> 5;
    const int bln = (bn0 << 2) | (bp & 3);
    const float* pW = w + bn0 * K_DIM + 2 * bp;

    float acc[8][4];
    #pragma unroll
    for (int i = 0; i < 8; i++)
        acc[i][0] = acc[i][1] = acc[i][2] = acc[i][3] = 0.f;

    // ---- prologue: async-issue A stages 0,1 ; convert B tile 0 ----
    #pragma unroll
    for (int ss = 0; ss < 8; ss++) {
        int idx = ss * THREADS + t;
        int r = idx >> 4, cc = idx & 15;
        cp16(aSmem + (0 * ASTAGE + r * ASTRIDE) * 4 + cc * 16,
             x + (rowBase + r) * K_DIM + 0 * TK + cc * 4);
    }
    asm volatile("cp.async.commit_group;");
    #pragma unroll
    for (int ss = 0; ss < 8; ss++) {
        int idx = ss * THREADS + t;
        int r = idx >> 4, cc = idx & 15;
        cp16(aSmem + (1 * ASTAGE + r * ASTRIDE) * 4 + cc * 16,
             x + (rowBase + r) * K_DIM + 1 * TK + cc * 4);
    }
    asm volatile("cp.async.commit_group;");

    #pragma unroll
    for (int i = 0; i < 8; i++) {
        float2 wv = *(const float2*)(pW + i * 8 * K_DIM);
        uint32_t h, l; split2(wv.x, wv.y, h, l);
        uint32_t* dst = Bst + (((bks * 8 + i) * 32 + bln) << 2);
        dst[brg] = h; dst[2 + brg] = l;
    }

    // ---- mainloop ----
    float2 wreg[8];
    for (int kt = 0; kt < NKT; kt++) {
        asm volatile("cp.async.wait_group %0;" :: "n"(1));
        __syncthreads();   // stage kt visible to all; B stage (kt&1) visible

        // issue A stage kt+2 (always commit to keep group accounting uniform)
        if (kt + 2 < NKT) {
            int s = (kt + 2) % NSTAGE;
            #pragma unroll
            for (int ss = 0; ss < 8; ss++) {
                int idx = ss * THREADS + t;
                int r = idx >> 4, cc = idx & 15;
                cp16(aSmem + (s * ASTAGE + r * ASTRIDE) * 4 + cc * 16,
                     x + (rowBase + r) * K_DIM + (kt + 2) * TK + cc * 4);
            }
        }
        asm volatile("cp.async.commit_group;");

        // prefetch w for next tile (L2-resident after first wave)
        if (kt + 1 < NKT) {
            #pragma unroll
            for (int i = 0; i < 8; i++)
                wreg[i] = *(const float2*)(pW + (kt + 1) * TK + i * 8 * K_DIM);
        }

        // read A fragments from SMEM, split to hi/lo bf16
        const float* As = smem + (kt % NSTAGE) * ASTAGE;
        uint32_t ah[4][4], al[4][4];
        #pragma unroll
        for (int ks = 0; ks < 4; ks++) {
            const float* p = As + (warpRow + g) * ASTRIDE + ks * 16 + 2 * q;
            float2 v0 = *(const float2*)(p);
            float2 v1 = *(const float2*)(p + 8 * ASTRIDE);
            float2 v2 = *(const float2*)(p + 8);
            float2 v3 = *(const float2*)(p + 8 * ASTRIDE + 8);
            split2(v0.x, v0.y, ah[ks][0], al[ks][0]);
            split2(v1.x, v1.y, ah[ks][1], al[ks][1]);
            split2(v2.x, v2.y, ah[ks][2], al[ks][2]);
            split2(v3.x, v3.y, ah[ks][3], al[ks][3]);
        }

        // MMAs: 4 ksteps x 8 n-tiles x 3 split terms
        const int sr = (kt & 1) ? BWORDS : 0;
        #pragma unroll
        for (int ks = 0; ks < 4; ks++) {
            #pragma unroll
            for (int tt = 0; tt < 8; tt++) {
                uint4 bf = *(const uint4*)(Bst + sr + (((ks * 8 + tt) * 32 + lane) << 2));
                mma16816(acc[tt], ah[ks][0], ah[ks][1], ah[ks][2], ah[ks][3], bf.x, bf.y);
                mma16816(acc[tt], ah[ks][0], ah[ks][1], ah[ks][2], ah[ks][3], bf.z, bf.w);
                mma16816(acc[tt], al[ks][0], al[ks][1], al[ks][2], al[ks][3], bf.x, bf.y);
            }
        }

        // convert + store B fragments for next tile into the other stage
        if (kt + 1 < NKT) {
            const int sw = ((kt + 1) & 1) ? BWORDS : 0;
            #pragma unroll
            for (int i = 0; i < 8; i++) {
                uint32_t h, l; split2(wreg[i].x, wreg[i].y, h, l);
                uint32_t* dst = Bst + sw + (((bks * 8 + i) * 32 + bln) << 2);
                dst[brg] = h; dst[2 + brg] = l;
            }
        }
    }
    __syncthreads();   // all MMA-side SMEM reads done before logits overwrite

    // ---- epilogue: bias + logits to SMEM ----
    float* L = smem;
    #pragma unroll
    for (int tt = 0; tt < 8; tt++) {
        int c = tt * 8 + 2 * q;
        float b0 = __ldg(&bias[c]);
        float b1 = __ldg(&bias[c + 1]);
        int r0 = warpRow + g;
        L[r0 * LDL + c]           = acc[tt][0] + b0;
        L[r0 * LDL + c + 1]       = acc[tt][1] + b1;
        L[(r0 + 8) * LDL + c]     = acc[tt][2] + b0;
        L[(r0 + 8) * LDL + c + 1] = acc[tt][3] + b1;
    }
    __syncthreads();

    // ---- routing: one thread per row ----
    if (t < TM) {
        bool any_immature = false;
        #pragma unroll 8
        for (int e = 0; e < N_EXP; e++)
            any_immature |= (__ldg(&mat[e]) == 0);

        float* row = &L[t * LDL];
        if (!any_immature) {
            float v1 = -__int_as_float(0x7f800000), v2 = v1;
            int i1 = 0, i2 = 0;
            #pragma unroll 8
            for (int e = 0; e < N_EXP; e++) {
                float v = row[e];
                if (v > v1)      { v2 = v1; i2 = i1; v1 = v; i1 = e; }
                else if (v > v2) { v2 = v;  i2 = e; }
            }
            float e2  = __expf(v2 - v1);
            float inv = 1.0f / (1.0f + e2);
            #pragma unroll 8
            for (int e = 0; e < N_EXP; e++) row[e] = 0.0f;
            row[i1] = inv;
            row[i2] = e2 * inv;
        } else {
            float m = -__int_as_float(0x7f800000);
            #pragma unroll 8
            for (int e = 0; e < N_EXP; e++) m = fmaxf(m, row[e]);
            float s = 0.0f;
            float tmp[N_EXP];
            #pragma unroll 8
            for (int e = 0; e < N_EXP; e++) {
                float v = __expf((row[e] - m) * (1.0f / TOPK_TEMP));
                tmp[e] = v; s += v;
            }
            float invs = 1.0f / s;
            #pragma unroll 8
            for (int e = 0; e < N_EXP; e++) row[e] = tmp[e] * invs;
        }
    }
    __syncthreads();

    // ---- coalesced float4 store of 128x64 tile ----
    #pragma unroll
    for (int s = 0; s < (TM * N_EXP / 4) / THREADS; s++) {   // 8
        int idx = s * THREADS + t;
        int r = idx >> 4;
        int c = (idx & 15) << 2;
        float4 v = *(const float4*)&L[r * LDL + c];
        *(float4*)(out + (rowBase + r) * N_EXP + c) = v;
    }
}

extern "C" void kernel_launch(void* const* d_in, const int* in_sizes, int n_in,
                              void* d_out, int out_size)
{
    const float* x   = (const float*)d_in[0];   // [16384, 2048]
    const float* w   = (const float*)d_in[1];   // [64, 2048]
    const float* b   = (const float*)d_in[2];   // [64]
    const int*   mat = (const int*)  d_in[3];   // [64]
    float* out = (float*)d_out;                 // [16384, 64]

    cudaFuncSetAttribute(dhr_mma_async_kernel,
                         cudaFuncAttributeMaxDynamicSharedMemorySize, SMEM_BYTES);

    int rows = in_sizes[0] / K_DIM;             // 16384
    int grid = rows / TM;                       // 128
    dhr_mma_async_kernel<<<grid, THREADS, SMEM_BYTES>>>(x, w, b, mat, out);
}

// round 5
// speedup vs baseline: 2.7302x; 1.0036x over previous
#include <cuda_runtime.h>
#include <cstdint>

#define K_DIM   2048
#define N_EXP   64
#define TM      128     // rows per CTA
#define TK      64      // K per tile
#define NKT     32      // K_DIM / TK
#define THREADS 512
#define ASTRIDE 72      // A smem row stride (floats)
#define ASTAGE  (TM * ASTRIDE)
#define NSTAGE  3
#define BWORDS  4096    // uint32 words per B stage
#define LDL     72
#define TOPK_TEMP 2.0f
#define SMEM_BYTES (NSTAGE * ASTAGE * 4 + 2 * BWORDS * 4)   // 143360

__device__ __forceinline__ uint32_t pack2(float f0, float f1) {
    uint32_t r;
    asm("cvt.rn.bf16x2.f32 %0, %1, %2;" : "=r"(r) : "f"(f1), "f"(f0));
    return r;
}
__device__ __forceinline__ void split2(float f0, float f1, uint32_t &h, uint32_t &l) {
    h = pack2(f0, f1);
    float h0 = __uint_as_float(h << 16);
    float h1 = __uint_as_float(h & 0xFFFF0000u);
    l = pack2(f0 - h0, f1 - h1);
}
__device__ __forceinline__ void mma16816(float *d,
                                         uint32_t a0, uint32_t a1, uint32_t a2, uint32_t a3,
                                         uint32_t b0, uint32_t b1) {
    asm volatile("mma.sync.aligned.m16n8k16.row.col.f32.bf16.bf16.f32 "
                 "{%0,%1,%2,%3}, {%4,%5,%6,%7}, {%8,%9}, {%0,%1,%2,%3};"
                 : "+f"(d[0]), "+f"(d[1]), "+f"(d[2]), "+f"(d[3])
                 : "r"(a0), "r"(a1), "r"(a2), "r"(a3), "r"(b0), "r"(b1));
}
__device__ __forceinline__ void cp16(uint32_t dst, const void* src) {
    asm volatile("cp.async.cg.shared.global [%0], [%1], 16;" :: "r"(dst), "l"(src));
}

__global__ __launch_bounds__(THREADS, 1)
void dhr_mma16_kernel(const float* __restrict__ x,
                      const float* __restrict__ w,
                      const float* __restrict__ bias,
                      const int*   __restrict__ mat,
                      float* __restrict__ out)
{
    extern __shared__ __align__(16) float smem[];
    uint32_t* Bst = (uint32_t*)(smem + NSTAGE * ASTAGE);

    const int t    = threadIdx.x;
    const int wid  = t >> 5;          // 0..15
    const int lane = t & 31;
    const int q    = lane & 3;
    const int g    = lane >> 2;
    const int nH   = wid >> 3;        // 0/1: experts 0-31 / 32-63
    const int warpRow = (wid & 7) * 16;
    const long rowBase = (long)blockIdx.x * TM;

    const uint32_t aSmem = (uint32_t)__cvta_generic_to_shared(smem);

    // B fill params (threads 0..255 only; validated R2/R3 fragment-order layout)
    const int bp  = t & 31;
    const int bks = bp >> 3;
    const int brg = (bp >> 2) & 1;
    const int bn0 = t >> 5;           // valid for t<256: 0..7
    const int bln = (bn0 << 2) | (bp & 3);
    const float* pW = w + bn0 * K_DIM + 2 * bp;
    const bool  doB = (t < 256);

    float acc[4][4];
    #pragma unroll
    for (int i = 0; i < 4; i++)
        acc[i][0] = acc[i][1] = acc[i][2] = acc[i][3] = 0.f;

    // ---- prologue: async A stages 0,1 ; B tile 0 ----
    #pragma unroll
    for (int ss = 0; ss < 4; ss++) {
        int idx = ss * THREADS + t;        // 0..2047
        int r = idx >> 4, cc = idx & 15;
        cp16(aSmem + (0 * ASTAGE + r * ASTRIDE) * 4 + cc * 16,
             x + (rowBase + r) * K_DIM + cc * 4);
    }
    asm volatile("cp.async.commit_group;");
    #pragma unroll
    for (int ss = 0; ss < 4; ss++) {
        int idx = ss * THREADS + t;
        int r = idx >> 4, cc = idx & 15;
        cp16(aSmem + (1 * ASTAGE + r * ASTRIDE) * 4 + cc * 16,
             x + (rowBase + r) * K_DIM + TK + cc * 4);
    }
    asm volatile("cp.async.commit_group;");

    if (doB) {
        #pragma unroll
        for (int i = 0; i < 8; i++) {
            float2 wv = *(const float2*)(pW + i * 8 * K_DIM);
            uint32_t h, l; split2(wv.x, wv.y, h, l);
            uint32_t* dst = Bst + (((bks * 8 + i) * 32 + bln) << 2);
            dst[brg] = h; dst[2 + brg] = l;
        }
    }

    // ---- mainloop ----
    float2 wreg[8];
    for (int kt = 0; kt < NKT; kt++) {
        asm volatile("cp.async.wait_group %0;" :: "n"(1));
        __syncthreads();

        if (kt + 2 < NKT) {
            int s = (kt + 2) % NSTAGE;
            #pragma unroll
            for (int ss = 0; ss < 4; ss++) {
                int idx = ss * THREADS + t;
                int r = idx >> 4, cc = idx & 15;
                cp16(aSmem + (s * ASTAGE + r * ASTRIDE) * 4 + cc * 16,
                     x + (rowBase + r) * K_DIM + (kt + 2) * TK + cc * 4);
            }
        }
        asm volatile("cp.async.commit_group;");

        if (doB && kt + 1 < NKT) {
            #pragma unroll
            for (int i = 0; i < 8; i++)
                wreg[i] = *(const float2*)(pW + (kt + 1) * TK + i * 8 * K_DIM);
        }

        // A fragments from SMEM -> hi/lo bf16
        const float* As = smem + (kt % NSTAGE) * ASTAGE;
        uint32_t ah[4][4], al[4][4];
        #pragma unroll
        for (int ks = 0; ks < 4; ks++) {
            const float* p = As + (warpRow + g) * ASTRIDE + ks * 16 + 2 * q;
            float2 v0 = *(const float2*)(p);
            float2 v1 = *(const float2*)(p + 8 * ASTRIDE);
            float2 v2 = *(const float2*)(p + 8);
            float2 v3 = *(const float2*)(p + 8 * ASTRIDE + 8);
            split2(v0.x, v0.y, ah[ks][0], al[ks][0]);
            split2(v1.x, v1.y, ah[ks][1], al[ks][1]);
            split2(v2.x, v2.y, ah[ks][2], al[ks][2]);
            split2(v3.x, v3.y, ah[ks][3], al[ks][3]);
        }

        // MMAs: 4 ksteps x 4 n-tiles (this warp's half) x 3 terms
        const int sr = (kt & 1) ? BWORDS : 0;
        #pragma unroll
        for (int ks = 0; ks < 4; ks++) {
            #pragma unroll
            for (int j = 0; j < 4; j++) {
                int tt = nH * 4 + j;
                uint4 bf = *(const uint4*)(Bst + sr + (((ks * 8 + tt) * 32 + lane) << 2));
                mma16816(acc[j], ah[ks][0], ah[ks][1], ah[ks][2], ah[ks][3], bf.x, bf.y);
                mma16816(acc[j], ah[ks][0], ah[ks][1], ah[ks][2], ah[ks][3], bf.z, bf.w);
                mma16816(acc[j], al[ks][0], al[ks][1], al[ks][2], al[ks][3], bf.x, bf.y);
            }
        }

        if (doB && kt + 1 < NKT) {
            const int sw = ((kt + 1) & 1) ? BWORDS : 0;
            #pragma unroll
            for (int i = 0; i < 8; i++) {
                uint32_t h, l; split2(wreg[i].x, wreg[i].y, h, l);
                uint32_t* dst = Bst + sw + (((bks * 8 + i) * 32 + bln) << 2);
                dst[brg] = h; dst[2 + brg] = l;
            }
        }
    }
    __syncthreads();   // all SMEM reads done before logits overwrite

    // ---- epilogue: bias + logits to SMEM ----
    float* L = smem;
    #pragma unroll
    for (int j = 0; j < 4; j++) {
        int c = (nH * 4 + j) * 8 + 2 * q;
        float b0 = __ldg(&bias[c]);
        float b1 = __ldg(&bias[c + 1]);
        int r0 = warpRow + g;
        L[r0 * LDL + c]           = acc[j][0] + b0;
        L[r0 * LDL + c + 1]       = acc[j][1] + b1;
        L[(r0 + 8) * LDL + c]     = acc[j][2] + b0;
        L[(r0 + 8) * LDL + c + 1] = acc[j][3] + b1;
    }
    __syncthreads();

    // ---- routing: one thread per row ----
    if (t < TM) {
        bool any_immature = false;
        #pragma unroll 8
        for (int e = 0; e < N_EXP; e++)
            any_immature |= (__ldg(&mat[e]) == 0);

        float* row = &L[t * LDL];
        if (!any_immature) {
            float v1 = -__int_as_float(0x7f800000), v2 = v1;
            int i1 = 0, i2 = 0;
            #pragma unroll 8
            for (int e = 0; e < N_EXP; e++) {
                float v = row[e];
                if (v > v1)      { v2 = v1; i2 = i1; v1 = v; i1 = e; }
                else if (v > v2) { v2 = v;  i2 = e; }
            }
            float e2  = __expf(v2 - v1);
            float inv = 1.0f / (1.0f + e2);
            #pragma unroll 8
            for (int e = 0; e < N_EXP; e++) row[e] = 0.0f;
            row[i1] = inv;
            row[i2] = e2 * inv;
        } else {
            float m = -__int_as_float(0x7f800000);
            #pragma unroll 8
            for (int e = 0; e < N_EXP; e++) m = fmaxf(m, row[e]);
            float s = 0.0f;
            float tmp[N_EXP];
            #pragma unroll 8
            for (int e = 0; e < N_EXP; e++) {
                float v = __expf((row[e] - m) * (1.0f / TOPK_TEMP));
                tmp[e] = v; s += v;
            }
            float invs = 1.0f / s;
            #pragma unroll 8
            for (int e = 0; e < N_EXP; e++) row[e] = tmp[e] * invs;
        }
    }
    __syncthreads();

    // ---- coalesced float4 store of 128x64 tile ----
    #pragma unroll
    for (int s = 0; s < (TM * N_EXP / 4) / THREADS; s++) {   // 4
        int idx = s * THREADS + t;
        int r = idx >> 4;
        int c = (idx & 15) << 2;
        float4 v = *(const float4*)&L[r * LDL + c];
        *(float4*)(out + (rowBase + r) * N_EXP + c) = v;
    }
}

extern "C" void kernel_launch(void* const* d_in, const int* in_sizes, int n_in,
                              void* d_out, int out_size)
{
    const float* x   = (const float*)d_in[0];   // [16384, 2048]
    const float* w   = (const float*)d_in[1];   // [64, 2048]
    const float* b   = (const float*)d_in[2];   // [64]
    const int*   mat = (const int*)  d_in[3];   // [64]
    float* out = (float*)d_out;                 // [16384, 64]

    cudaFuncSetAttribute(dhr_mma16_kernel,
                         cudaFuncAttributeMaxDynamicSharedMemorySize, SMEM_BYTES);

    int rows = in_sizes[0] / K_DIM;             // 16384
    int grid = rows / TM;                       // 128
    dhr_mma16_kernel<<<grid, THREADS, SMEM_BYTES>>>(x, w, b, mat, out);
}

// round 6
// speedup vs baseline: 2.9179x; 1.0688x over previous
#include <cuda_runtime.h>
#include <cstdint>

#define K_DIM   2048
#define N_EXP   64
#define TM      128     // rows per CTA
#define TK      64      // K per tile
#define NKT     32      // K_DIM / TK
#define THREADS 256
#define ASTRIDE 72      // A smem row stride (floats)
#define ASTAGE  (TM * ASTRIDE)       // floats per A stage
#define NSTAGE  3
#define BWORDS  4096                 // uint32 words per B stage (16KB)
#define LDL     72
#define TOPK_TEMP 2.0f
#define SMEM_BYTES (NSTAGE * ASTAGE * 4 + NSTAGE * BWORDS * 4)   // 159744

// Pre-converted w fragments: [NKT][BWORDS] uint32 (hi/lo bf16, mma fragment order)
__device__ uint32_t g_wfrag[NKT * BWORDS];

__device__ __forceinline__ uint32_t pack2(float f0, float f1) {
    uint32_t r;
    asm("cvt.rn.bf16x2.f32 %0, %1, %2;" : "=r"(r) : "f"(f1), "f"(f0));
    return r;
}
__device__ __forceinline__ void split2(float f0, float f1, uint32_t &h, uint32_t &l) {
    h = pack2(f0, f1);
    float h0 = __uint_as_float(h << 16);
    float h1 = __uint_as_float(h & 0xFFFF0000u);
    l = pack2(f0 - h0, f1 - h1);
}
__device__ __forceinline__ void mma16816(float *d,
                                         uint32_t a0, uint32_t a1, uint32_t a2, uint32_t a3,
                                         uint32_t b0, uint32_t b1) {
    asm volatile("mma.sync.aligned.m16n8k16.row.col.f32.bf16.bf16.f32 "
                 "{%0,%1,%2,%3}, {%4,%5,%6,%7}, {%8,%9}, {%0,%1,%2,%3};"
                 : "+f"(d[0]), "+f"(d[1]), "+f"(d[2]), "+f"(d[3])
                 : "r"(a0), "r"(a1), "r"(a2), "r"(a3), "r"(b0), "r"(b1));
}
__device__ __forceinline__ void cp16(uint32_t dst, const void* src) {
    asm volatile("cp.async.cg.shared.global [%0], [%1], 16;" :: "r"(dst), "l"(src));
}

// ---- prep: convert w -> bf16 hi/lo fragments in gmem (validated layout) ----
__global__ __launch_bounds__(256)
void dhr_wprep_kernel(const float* __restrict__ w)
{
    const int kt = blockIdx.x;
    const int t  = threadIdx.x;
    const int bp  = t & 31;
    const int bks = bp >> 3;
    const int brg = (bp >> 2) & 1;
    const int bn0 = t >> 5;
    const int bln = (bn0 << 2) | (bp & 3);
    const float* pW = w + bn0 * K_DIM + kt * TK + 2 * bp;
    uint32_t* dst0 = g_wfrag + kt * BWORDS;
    #pragma unroll
    for (int i = 0; i < 8; i++) {
        float2 wv = *(const float2*)(pW + i * 8 * K_DIM);
        uint32_t h, l; split2(wv.x, wv.y, h, l);
        uint32_t* d = dst0 + (((bks * 8 + i) * 32 + bln) << 2);
        d[brg] = h; d[2 + brg] = l;
    }
}

__global__ __launch_bounds__(THREADS, 1)
void dhr_mma_m32_kernel(const float* __restrict__ x,
                        const float* __restrict__ bias,
                        const int*   __restrict__ mat,
                        float* __restrict__ out)
{
    extern __shared__ __align__(16) float smem[];
    uint32_t* Bbase = (uint32_t*)(smem + NSTAGE * ASTAGE);

    const int t    = threadIdx.x;
    const int wid  = t >> 5;          // 0..7
    const int lane = t & 31;
    const int q    = lane & 3;
    const int g    = lane >> 2;
    const int st4  = (wid & 3) * 32;  // row stripe base (32 rows)
    const int nH   = wid >> 2;        // 0/1: experts 0-31 / 32-63
    const long rowBase = (long)blockIdx.x * TM;

    const uint32_t aSmem = (uint32_t)__cvta_generic_to_shared(smem);
    const uint32_t bSmem = (uint32_t)__cvta_generic_to_shared(Bbase);

    float acc[2][4][4];
    #pragma unroll
    for (int m = 0; m < 2; m++)
        #pragma unroll
        for (int j = 0; j < 4; j++)
            acc[m][j][0] = acc[m][j][1] = acc[m][j][2] = acc[m][j][3] = 0.f;

    // ---- prologue: issue stages 0,1 (A + B together per group) ----
    #pragma unroll
    for (int s0 = 0; s0 < 2; s0++) {
        #pragma unroll
        for (int ss = 0; ss < 8; ss++) {
            int idx = ss * THREADS + t;        // 0..2047
            int r = idx >> 4, cc = idx & 15;
            cp16(aSmem + (s0 * ASTAGE + r * ASTRIDE) * 4 + cc * 16,
                 x + (rowBase + r) * K_DIM + s0 * TK + cc * 4);
        }
        #pragma unroll
        for (int ss = 0; ss < 4; ss++) {
            int idx = ss * THREADS + t;        // 0..1023 16B chunks
            cp16(bSmem + s0 * BWORDS * 4 + idx * 16,
                 g_wfrag + s0 * BWORDS + idx * 4);
        }
        asm volatile("cp.async.commit_group;");
    }

    // ---- mainloop ----
    for (int kt = 0; kt < NKT; kt++) {
        asm volatile("cp.async.wait_group %0;" :: "n"(1));
        __syncthreads();

        if (kt + 2 < NKT) {
            int s = (kt + 2) % NSTAGE;
            #pragma unroll
            for (int ss = 0; ss < 8; ss++) {
                int idx = ss * THREADS + t;
                int r = idx >> 4, cc = idx & 15;
                cp16(aSmem + (s * ASTAGE + r * ASTRIDE) * 4 + cc * 16,
                     x + (rowBase + r) * K_DIM + (kt + 2) * TK + cc * 4);
            }
            #pragma unroll
            for (int ss = 0; ss < 4; ss++) {
                int idx = ss * THREADS + t;
                cp16(bSmem + s * BWORDS * 4 + idx * 16,
                     g_wfrag + (kt + 2) * BWORDS + idx * 4);
            }
        }
        asm volatile("cp.async.commit_group;");

        const float*    As = smem + (kt % NSTAGE) * ASTAGE;
        const uint32_t* Bs = Bbase + (kt % NSTAGE) * BWORDS;

        #pragma unroll
        for (int ks = 0; ks < 4; ks++) {
            // A fragments for 2 m-tiles (rows st4+g{,+8,+16,+24})
            const float* p = As + (st4 + g) * ASTRIDE + ks * 16 + 2 * q;
            uint32_t ah[2][4], al[2][4];
            #pragma unroll
            for (int m = 0; m < 2; m++) {
                const float* pm = p + m * 16 * ASTRIDE;
                float2 v0 = *(const float2*)(pm);
                float2 v1 = *(const float2*)(pm + 8 * ASTRIDE);
                float2 v2 = *(const float2*)(pm + 8);
                float2 v3 = *(const float2*)(pm + 8 * ASTRIDE + 8);
                split2(v0.x, v0.y, ah[m][0], al[m][0]);
                split2(v1.x, v1.y, ah[m][1], al[m][1]);
                split2(v2.x, v2.y, ah[m][2], al[m][2]);
                split2(v3.x, v3.y, ah[m][3], al[m][3]);
            }
            // each B uint4 feeds 6 MMAs (2 m-tiles x 3 terms)
            #pragma unroll
            for (int j = 0; j < 4; j++) {
                int tt = nH * 4 + j;
                uint4 bf = *(const uint4*)(Bs + (((ks * 8 + tt) * 32 + lane) << 2));
                #pragma unroll
                for (int m = 0; m < 2; m++) {
                    mma16816(acc[m][j], ah[m][0], ah[m][1], ah[m][2], ah[m][3], bf.x, bf.y);
                    mma16816(acc[m][j], ah[m][0], ah[m][1], ah[m][2], ah[m][3], bf.z, bf.w);
                    mma16816(acc[m][j], al[m][0], al[m][1], al[m][2], al[m][3], bf.x, bf.y);
                }
            }
        }
    }
    __syncthreads();

    // ---- epilogue: bias + logits to SMEM ----
    float* L = smem;
    #pragma unroll
    for (int m = 0; m < 2; m++) {
        #pragma unroll
        for (int j = 0; j < 4; j++) {
            int c = (nH * 4 + j) * 8 + 2 * q;
            float b0 = __ldg(&bias[c]);
            float b1 = __ldg(&bias[c + 1]);
            int r0 = st4 + g + 16 * m;
            L[r0 * LDL + c]           = acc[m][j][0] + b0;
            L[r0 * LDL + c + 1]       = acc[m][j][1] + b1;
            L[(r0 + 8) * LDL + c]     = acc[m][j][2] + b0;
            L[(r0 + 8) * LDL + c + 1] = acc[m][j][3] + b1;
        }
    }
    __syncthreads();

    // ---- routing: one thread per row ----
    if (t < TM) {
        bool any_immature = false;
        #pragma unroll 8
        for (int e = 0; e < N_EXP; e++)
            any_immature |= (__ldg(&mat[e]) == 0);

        float* row = &L[t * LDL];
        if (!any_immature) {
            float v1 = -__int_as_float(0x7f800000), v2 = v1;
            int i1 = 0, i2 = 0;
            #pragma unroll 8
            for (int e = 0; e < N_EXP; e++) {
                float v = row[e];
                if (v > v1)      { v2 = v1; i2 = i1; v1 = v; i1 = e; }
                else if (v > v2) { v2 = v;  i2 = e; }
            }
            float e2  = __expf(v2 - v1);
            float inv = 1.0f / (1.0f + e2);
            #pragma unroll 8
            for (int e = 0; e < N_EXP; e++) row[e] = 0.0f;
            row[i1] = inv;
            row[i2] = e2 * inv;
        } else {
            float m = -__int_as_float(0x7f800000);
            #pragma unroll 8
            for (int e = 0; e < N_EXP; e++) m = fmaxf(m, row[e]);
            float s = 0.0f;
            float tmp[N_EXP];
            #pragma unroll 8
            for (int e = 0; e < N_EXP; e++) {
                float v = __expf((row[e] - m) * (1.0f / TOPK_TEMP));
                tmp[e] = v; s += v;
            }
            float invs = 1.0f / s;
            #pragma unroll 8
            for (int e = 0; e < N_EXP; e++) row[e] = tmp[e] * invs;
        }
    }
    __syncthreads();

    // ---- coalesced float4 store of 128x64 tile ----
    #pragma unroll
    for (int s = 0; s < (TM * N_EXP / 4) / THREADS; s++) {   // 8
        int idx = s * THREADS + t;
        int r = idx >> 4;
        int c = (idx & 15) << 2;
        float4 v = *(const float4*)&L[r * LDL + c];
        *(float4*)(out + (rowBase + r) * N_EXP + c) = v;
    }
}

extern "C" void kernel_launch(void* const* d_in, const int* in_sizes, int n_in,
                              void* d_out, int out_size)
{
    const float* x   = (const float*)d_in[0];   // [16384, 2048]
    const float* w   = (const float*)d_in[1];   // [64, 2048]
    const float* b   = (const float*)d_in[2];   // [64]
    const int*   mat = (const int*)  d_in[3];   // [64]
    float* out = (float*)d_out;                 // [16384, 64]

    cudaFuncSetAttribute(dhr_mma_m32_kernel,
                         cudaFuncAttributeMaxDynamicSharedMemorySize, SMEM_BYTES);

    dhr_wprep_kernel<<<NKT, 256>>>(w);

    int rows = in_sizes[0] / K_DIM;             // 16384
    int grid = rows / TM;                       // 128
    dhr_mma_m32_kernel<<<grid, THREADS, SMEM_BYTES>>>(x, b, mat, out);
}

// round 7
// speedup vs baseline: 3.0166x; 1.0338x over previous
#include <cuda_runtime.h>
#include <cstdint>

#define K_DIM   2048
#define N_EXP   64
#define TM      128     // rows per CTA
#define TK      64      // K per tile
#define NKT     32      // K_DIM / TK
#define THREADS 512
#define ASTRIDE 72      // A smem row stride (floats)
#define ASTAGE  (TM * ASTRIDE)       // floats per A stage
#define NSTAGE  3
#define BWORDS  4096                 // uint32 words per B stage (16KB)
#define LDL     72
#define TOPK_TEMP 2.0f
#define SMEM_BYTES (NSTAGE * ASTAGE * 4 + NSTAGE * BWORDS * 4)   // 159744

// Pre-converted w fragments: [NKT][BWORDS] uint32 (hi/lo bf16, mma fragment order)
__device__ uint32_t g_wfrag[NKT * BWORDS];

__device__ __forceinline__ uint32_t pack2(float f0, float f1) {
    uint32_t r;
    asm("cvt.rn.bf16x2.f32 %0, %1, %2;" : "=r"(r) : "f"(f1), "f"(f0));
    return r;
}
__device__ __forceinline__ void split2(float f0, float f1, uint32_t &h, uint32_t &l) {
    h = pack2(f0, f1);
    float h0 = __uint_as_float(h << 16);
    float h1 = __uint_as_float(h & 0xFFFF0000u);
    l = pack2(f0 - h0, f1 - h1);
}
__device__ __forceinline__ void mma16816(float *d,
                                         uint32_t a0, uint32_t a1, uint32_t a2, uint32_t a3,
                                         uint32_t b0, uint32_t b1) {
    asm volatile("mma.sync.aligned.m16n8k16.row.col.f32.bf16.bf16.f32 "
                 "{%0,%1,%2,%3}, {%4,%5,%6,%7}, {%8,%9}, {%0,%1,%2,%3};"
                 : "+f"(d[0]), "+f"(d[1]), "+f"(d[2]), "+f"(d[3])
                 : "r"(a0), "r"(a1), "r"(a2), "r"(a3), "r"(b0), "r"(b1));
}
__device__ __forceinline__ void cp16(uint32_t dst, const void* src) {
    asm volatile("cp.async.cg.shared.global [%0], [%1], 16;" :: "r"(dst), "l"(src));
}

// ---- prep: convert w -> bf16 hi/lo fragments in gmem (validated layout) ----
__global__ __launch_bounds__(256)
void dhr_wprep_kernel(const float* __restrict__ w)
{
    const int kt = blockIdx.x;
    const int t  = threadIdx.x;
    const int bp  = t & 31;
    const int bks = bp >> 3;
    const int brg = (bp >> 2) & 1;
    const int bn0 = t >> 5;
    const int bln = (bn0 << 2) | (bp & 3);
    const float* pW = w + bn0 * K_DIM + kt * TK + 2 * bp;
    uint32_t* dst0 = g_wfrag + kt * BWORDS;
    #pragma unroll
    for (int i = 0; i < 8; i++) {
        float2 wv = *(const float2*)(pW + i * 8 * K_DIM);
        uint32_t h, l; split2(wv.x, wv.y, h, l);
        uint32_t* d = dst0 + (((bks * 8 + i) * 32 + bln) << 2);
        d[brg] = h; d[2 + brg] = l;
    }
}

__global__ __launch_bounds__(THREADS, 1)
void dhr_ksplit_kernel(const float* __restrict__ x,
                       const float* __restrict__ bias,
                       const int*   __restrict__ mat,
                       float* __restrict__ out)
{
    extern __shared__ __align__(16) float smem[];
    uint32_t* Bbase = (uint32_t*)(smem + NSTAGE * ASTAGE);

    const int t    = threadIdx.x;
    const int wid  = t >> 5;              // 0..15
    const int lane = t & 31;
    const int q    = lane & 3;
    const int g    = lane >> 2;
    const int kh     = wid & 1;           // k-half: ks in {2kh, 2kh+1}
    const int stripe = (wid >> 1) & 3;    // rows stripe*32 .. +31
    const int nH     = wid >> 3;          // experts nH*32 .. +31
    const int mrow   = stripe * 32;
    const long rowBase = (long)blockIdx.x * TM;

    const uint32_t aSmem = (uint32_t)__cvta_generic_to_shared(smem);
    const uint32_t bSmem = (uint32_t)__cvta_generic_to_shared(Bbase);

    float acc[2][4][4];
    #pragma unroll
    for (int m = 0; m < 2; m++)
        #pragma unroll
        for (int j = 0; j < 4; j++)
            acc[m][j][0] = acc[m][j][1] = acc[m][j][2] = acc[m][j][3] = 0.f;

    // ---- prologue: issue stages 0,1 (A + B per group) ----
    #pragma unroll
    for (int s0 = 0; s0 < 2; s0++) {
        #pragma unroll
        for (int ss = 0; ss < 4; ss++) {
            int idx = ss * THREADS + t;        // 0..2047
            int r = idx >> 4, cc = idx & 15;
            cp16(aSmem + (s0 * ASTAGE + r * ASTRIDE) * 4 + cc * 16,
                 x + (rowBase + r) * K_DIM + s0 * TK + cc * 4);
        }
        #pragma unroll
        for (int ss = 0; ss < 2; ss++) {
            int idx = ss * THREADS + t;        // 0..1023 16B chunks
            cp16(bSmem + s0 * BWORDS * 4 + idx * 16,
                 g_wfrag + s0 * BWORDS + idx * 4);
        }
        asm volatile("cp.async.commit_group;");
    }

    // ---- mainloop ----
    for (int kt = 0; kt < NKT; kt++) {
        asm volatile("cp.async.wait_group %0;" :: "n"(1));
        __syncthreads();

        if (kt + 2 < NKT) {
            int s = (kt + 2) % NSTAGE;
            #pragma unroll
            for (int ss = 0; ss < 4; ss++) {
                int idx = ss * THREADS + t;
                int r = idx >> 4, cc = idx & 15;
                cp16(aSmem + (s * ASTAGE + r * ASTRIDE) * 4 + cc * 16,
                     x + (rowBase + r) * K_DIM + (kt + 2) * TK + cc * 4);
            }
            #pragma unroll
            for (int ss = 0; ss < 2; ss++) {
                int idx = ss * THREADS + t;
                cp16(bSmem + s * BWORDS * 4 + idx * 16,
                     g_wfrag + (kt + 2) * BWORDS + idx * 4);
            }
        }
        asm volatile("cp.async.commit_group;");

        const float*    As = smem + (kt % NSTAGE) * ASTAGE;
        const uint32_t* Bs = Bbase + (kt % NSTAGE) * BWORDS;

        #pragma unroll
        for (int kk = 0; kk < 2; kk++) {
            const int ks = kh * 2 + kk;
            // A fragments for this warp's 2 m-tiles
            const float* p = As + (mrow + g) * ASTRIDE + ks * 16 + 2 * q;
            uint32_t ah[2][4], al[2][4];
            #pragma unroll
            for (int m = 0; m < 2; m++) {
                const float* pm = p + m * 16 * ASTRIDE;
                float2 v0 = *(const float2*)(pm);
                float2 v1 = *(const float2*)(pm + 8 * ASTRIDE);
                float2 v2 = *(const float2*)(pm + 8);
                float2 v3 = *(const float2*)(pm + 8 * ASTRIDE + 8);
                split2(v0.x, v0.y, ah[m][0], al[m][0]);
                split2(v1.x, v1.y, ah[m][1], al[m][1]);
                split2(v2.x, v2.y, ah[m][2], al[m][2]);
                split2(v3.x, v3.y, ah[m][3], al[m][3]);
            }
            // each B uint4 feeds 6 MMAs (2 m-tiles x 3 terms)
            #pragma unroll
            for (int j = 0; j < 4; j++) {
                int tt = nH * 4 + j;
                uint4 bf = *(const uint4*)(Bs + (((ks * 8 + tt) * 32 + lane) << 2));
                #pragma unroll
                for (int m = 0; m < 2; m++) {
                    mma16816(acc[m][j], ah[m][0], ah[m][1], ah[m][2], ah[m][3], bf.x, bf.y);
                    mma16816(acc[m][j], ah[m][0], ah[m][1], ah[m][2], ah[m][3], bf.z, bf.w);
                    mma16816(acc[m][j], al[m][0], al[m][1], al[m][2], al[m][3], bf.x, bf.y);
                }
            }
        }
    }
    __syncthreads();

    // ---- epilogue: combine K-split partials + bias into SMEM logits ----
    float* L = smem;
    if (kh == 0) {
        #pragma unroll
        for (int m = 0; m < 2; m++) {
            #pragma unroll
            for (int j = 0; j < 4; j++) {
                int c = (nH * 4 + j) * 8 + 2 * q;
                float b0 = __ldg(&bias[c]);
                float b1 = __ldg(&bias[c + 1]);
                int r0 = mrow + g + 16 * m;
                L[r0 * LDL + c]           = acc[m][j][0] + b0;
                L[r0 * LDL + c + 1]       = acc[m][j][1] + b1;
                L[(r0 + 8) * LDL + c]     = acc[m][j][2] + b0;
                L[(r0 + 8) * LDL + c + 1] = acc[m][j][3] + b1;
            }
        }
    }
    __syncthreads();
    if (kh == 1) {
        #pragma unroll
        for (int m = 0; m < 2; m++) {
            #pragma unroll
            for (int j = 0; j < 4; j++) {
                int c = (nH * 4 + j) * 8 + 2 * q;
                int r0 = mrow + g + 16 * m;
                L[r0 * LDL + c]           += acc[m][j][0];
                L[r0 * LDL + c + 1]       += acc[m][j][1];
                L[(r0 + 8) * LDL + c]     += acc[m][j][2];
                L[(r0 + 8) * LDL + c + 1] += acc[m][j][3];
            }
        }
    }
    __syncthreads();

    // ---- routing: one thread per row ----
    if (t < TM) {
        bool any_immature = false;
        #pragma unroll 8
        for (int e = 0; e < N_EXP; e++)
            any_immature |= (__ldg(&mat[e]) == 0);

        float* row = &L[t * LDL];
        if (!any_immature) {
            float v1 = -__int_as_float(0x7f800000), v2 = v1;
            int i1 = 0, i2 = 0;
            #pragma unroll 8
            for (int e = 0; e < N_EXP; e++) {
                float v = row[e];
                if (v > v1)      { v2 = v1; i2 = i1; v1 = v; i1 = e; }
                else if (v > v2) { v2 = v;  i2 = e; }
            }
            float e2  = __expf(v2 - v1);
            float inv = 1.0f / (1.0f + e2);
            #pragma unroll 8
            for (int e = 0; e < N_EXP; e++) row[e] = 0.0f;
            row[i1] = inv;
            row[i2] = e2 * inv;
        } else {
            float m = -__int_as_float(0x7f800000);
            #pragma unroll 8
            for (int e = 0; e < N_EXP; e++) m = fmaxf(m, row[e]);
            float s = 0.0f;
            float tmp[N_EXP];
            #pragma unroll 8
            for (int e = 0; e < N_EXP; e++) {
                float v = __expf((row[e] - m) * (1.0f / TOPK_TEMP));
                tmp[e] = v; s += v;
            }
            float invs = 1.0f / s;
            #pragma unroll 8
            for (int e = 0; e < N_EXP; e++) row[e] = tmp[e] * invs;
        }
    }
    __syncthreads();

    // ---- coalesced float4 store of 128x64 tile ----
    #pragma unroll
    for (int s = 0; s < (TM * N_EXP / 4) / THREADS; s++) {   // 4
        int idx = s * THREADS + t;
        int r = idx >> 4;
        int c = (idx & 15) << 2;
        float4 v = *(const float4*)&L[r * LDL + c];
        *(float4*)(out + (rowBase + r) * N_EXP + c) = v;
    }
}

extern "C" void kernel_launch(void* const* d_in, const int* in_sizes, int n_in,
                              void* d_out, int out_size)
{
    const float* x   = (const float*)d_in[0];   // [16384, 2048]
    const float* w   = (const float*)d_in[1];   // [64, 2048]
    const float* b   = (const float*)d_in[2];   // [64]
    const int*   mat = (const int*)  d_in[3];   // [64]
    float* out = (float*)d_out;                 // [16384, 64]

    cudaFuncSetAttribute(dhr_ksplit_kernel,
                         cudaFuncAttributeMaxDynamicSharedMemorySize, SMEM_BYTES);

    dhr_wprep_kernel<<<NKT, 256>>>(w);

    int rows = in_sizes[0] / K_DIM;             // 16384
    int grid = rows / TM;                       // 128
    dhr_ksplit_kernel<<<grid, THREADS, SMEM_BYTES>>>(x, b, mat, out);
}